// round 16
// baseline (speedup 1.0000x reference)
#include <cuda_runtime.h>
#include <cuda_bf16.h>
#include <cstdint>

#define B_N   32
#define CIN   256
#define HW    3136
#define HW4   784
#define PX    100352          // B_N*HW
#define CO1   128
#define CO2   32
#define N_OUT (32*288*3136)

// ---------------- scratch (device globals; no allocations) ----------------
__device__ float    g_bf[CO1], g_sw1[CO1];
__device__ __nv_bfloat16 g_w1cb[CO1*256];   // conv1 weight codes bf16 [oc][k]
__device__ float    g_sw2[CO2];
__device__ __nv_bfloat16 g_w2cb[CO2*1160];  // conv2 weight codes bf16 [oc][tap*128+ci]
__device__ float    g_pmax1[8192], g_pmaxb[8192];   // per-block partials (no init needed)
__device__ float    g_pmax2[784];
__device__ float    g_pmaxy[896];
__device__ float    g_maxb_f;                        // same-value multi-writer
__device__ float    g_x2[PX*CO1];           // conv1 out fp32 NHWC (51.4MB)

// ---------------- helpers ----------------
__device__ __forceinline__ float warpMax(float v) {
    #pragma unroll
    for (int o = 16; o; o >>= 1) v = fmaxf(v, __shfl_xor_sync(0xffffffffu, v, o));
    return v;
}
__device__ __forceinline__ float blockReduceMax(float v) {
    __shared__ float sm[16];
    float w = warpMax(v);
    if ((threadIdx.x & 31) == 0) sm[threadIdx.x >> 5] = w;
    __syncthreads();
    float r = (threadIdx.x < (blockDim.x >> 5)) ? sm[threadIdx.x] : 0.0f;
    r = warpMax(r);
    __syncthreads();
    return r;  // valid in warp 0
}
__device__ __forceinline__ float qclipf(float q, float lo, float hi) {
    return fminf(fmaxf(q, lo), hi);
}
__device__ __forceinline__ uint32_t smem_u32(const void* p) {
    return (uint32_t)__cvta_generic_to_shared(p);
}
__device__ __forceinline__ void ldsm_x4(uint32_t& r0, uint32_t& r1,
                                        uint32_t& r2, uint32_t& r3, uint32_t a) {
    asm volatile("ldmatrix.sync.aligned.m8n8.x4.shared.b16 {%0,%1,%2,%3}, [%4];"
                 : "=r"(r0), "=r"(r1), "=r"(r2), "=r"(r3) : "r"(a));
}
__device__ __forceinline__ void mma_bf16(float* d, const uint32_t* a, const uint32_t* b) {
    asm volatile(
        "mma.sync.aligned.m16n8k16.row.col.f32.bf16.bf16.f32 "
        "{%0,%1,%2,%3},{%4,%5,%6,%7},{%8,%9},{%0,%1,%2,%3};"
        : "+f"(d[0]), "+f"(d[1]), "+f"(d[2]), "+f"(d[3])
        : "r"(a[0]), "r"(a[1]), "r"(a[2]), "r"(a[3]), "r"(b[0]), "r"(b[1]));
}
__device__ __forceinline__ void cp16(uint32_t dst, const void* src) {
    asm volatile("cp.async.cg.shared.global [%0], [%1], 16;" :: "r"(dst), "l"(src));
}
__device__ __forceinline__ void cp_commit() {
    asm volatile("cp.async.commit_group;");
}
__device__ __forceinline__ void cp_wait0() {
    asm volatile("cp.async.wait_group 0;" ::: "memory");
}
__device__ __forceinline__ void bar_sync256(int id) {
    asm volatile("bar.sync %0, 256;" :: "r"(id) : "memory");
}
__device__ __forceinline__ void bar_arrive256(int id) {
    asm volatile("bar.arrive %0, 256;" :: "r"(id) : "memory");
}

// ---- K1: max relu(bn1(batch)) + max|batch| per plane, plus weight-prep blocks ----
__global__ __launch_bounds__(256) void k_max1(
    const float4* __restrict__ batch4,
    const float* __restrict__ g1, const float* __restrict__ be1,
    const float* __restrict__ m1, const float* __restrict__ v1,
    const float* __restrict__ s_in_p,
    const float* __restrict__ w1c, const float* __restrict__ g2,
    const float* __restrict__ be2, const float* __restrict__ m2,
    const float* __restrict__ v2, const float* __restrict__ w2c)
{
    int ci = blockIdx.x, b = blockIdx.y;
    int t = threadIdx.x;
    int w = t >> 5, l = t & 31;

    if (ci >= CIN) {
        if (b) return;
        if (ci == CIN) {
            for (int o = w; o < CO1; o += 8) {
                float tt = g2[o] / sqrtf(v2[o] + 1e-5f);
                const float* wr = w1c + o * CIN;
                float mx = 0.0f;
                #pragma unroll
                for (int i = 0; i < 8; i++) mx = fmaxf(mx, fabsf(wr[l + 32 * i] * tt));
                mx = warpMax(mx);
                float s = mx / 127.0f + 1e-8f;
                if (l == 0) { g_sw1[o] = s; g_bf[o] = be2[o] - m2[o] * tt; }
                #pragma unroll
                for (int i = 0; i < 8; i++) {
                    int c = l + 32 * i;
                    float code = qclipf(rintf(wr[c] * tt / s), -128.0f, 127.0f);
                    g_w1cb[o * 256 + c] = __float2bfloat16(code);
                }
            }
        } else {
            for (int o = w; o < CO2; o += 8) {
                const float* wr = w2c + o * 1152;
                float mx = 0.0f;
                #pragma unroll
                for (int i = 0; i < 36; i++) mx = fmaxf(mx, fabsf(wr[l + 32 * i]));
                mx = warpMax(mx);
                float s = mx / 127.0f + 1e-8f;
                if (l == 0) g_sw2[o] = s;
                #pragma unroll
                for (int i = 0; i < 36; i++) {
                    int j = l + 32 * i;
                    int tap = j >> 7, cc = j & 127;
                    float code = qclipf(rintf(wr[cc * 9 + tap] / s), -128.0f, 127.0f);
                    g_w2cb[o * 1160 + j] = __float2bfloat16(code);
                }
            }
        }
        return;
    }

    // bn1 fold (in-block, bit-identical)
    float w1t = g1[t] / sqrtf(v1[t] + 1e-5f);
    float bm = blockReduceMax(fabsf(w1t));
    __shared__ float s_sbn;
    if (t == 0) s_sbn = bm / 127.0f + 1e-8f;
    __syncthreads();
    float sbn = s_sbn;
    float w1i = g1[ci] / sqrtf(v1[ci] + 1e-5f);
    float b1i = be1[ci] - m1[ci] * w1i;
    float wq = qclipf(rintf(w1i / sbn), -128.0f, 127.0f) * sbn;
    float scb = s_in_p[0] * sbn;
    float bq = rintf(b1i / scb) * scb;

    const float4* p = batch4 + (b * CIN + ci) * HW4;
    float4 v0 = p[t], vA = p[t + 256], vB = p[t + 512];
    bool has3 = t < (HW4 - 768);
    float4 vC = has3 ? p[t + 768] : make_float4(0.0f, 0.0f, 0.0f, 0.0f);
    float m1v = 0.0f, mb = 0.0f;
    #define M1(v) do { \
        m1v = fmaxf(m1v, fmaxf(fmaf(v.x, wq, bq), 0.0f)); \
        m1v = fmaxf(m1v, fmaxf(fmaf(v.y, wq, bq), 0.0f)); \
        m1v = fmaxf(m1v, fmaxf(fmaf(v.z, wq, bq), 0.0f)); \
        m1v = fmaxf(m1v, fmaxf(fmaf(v.w, wq, bq), 0.0f)); \
        mb = fmaxf(mb, fmaxf(fmaxf(fabsf(v.x), fabsf(v.y)), \
                             fmaxf(fabsf(v.z), fabsf(v.w)))); } while (0)
    M1(v0); M1(vA); M1(vB);
    if (has3) M1(vC);
    #undef M1
    float r1 = blockReduceMax(m1v);
    if (t == 0) g_pmax1[b * CIN + ci] = r1;
    float rb = blockReduceMax(mb);
    if (t == 0) g_pmaxb[b * CIN + ci] = rb;
}

// ---- K2: fused bn1+quant + 1x1 conv via bf16 mma (128px x 128oc, K=256) ----
__global__ __launch_bounds__(256, 2) void k_conv1(
    const float* __restrict__ batch,
    const float* __restrict__ g1, const float* __restrict__ be1,
    const float* __restrict__ m1, const float* __restrict__ v1,
    const float* __restrict__ s_in_p)
{
    extern __shared__ __nv_bfloat16 smemb[];
    __nv_bfloat16* Xs = smemb;                          // [128 px][264]
    __nv_bfloat16* Wb = smemb + 128 * 264;              // [2][128 oc][72]
    float* sc1  = (float*)(smemb + 128 * 264 + 2 * 128 * 72);
    float* sb1  = sc1 + 128;
    float* sw1s = sb1 + 128;                            // 256
    float* sb1s = sw1s + 256;                           // 256
    int t = threadIdx.x;
    int p0 = blockIdx.x * 128;

    // reduce partials: sa1 + maxb (service for k_out)
    float a1 = 0.0f, ab = 0.0f;
    #pragma unroll 4
    for (int i = t; i < 8192; i += 256) {
        a1 = fmaxf(a1, g_pmax1[i]);
        ab = fmaxf(ab, g_pmaxb[i]);
    }
    float r1 = blockReduceMax(a1);
    __shared__ float s_sa1;
    if (t == 0) s_sa1 = r1 / 127.0f + 1e-8f;
    float rb = blockReduceMax(ab);
    if (t == 0) g_maxb_f = rb;          // identical value from every block

    // bn1 fold into smem (bit-identical math)
    float w1t = g1[t] / sqrtf(v1[t] + 1e-5f);
    float b1t = be1[t] - m1[t] * w1t;
    float bm = blockReduceMax(fabsf(w1t));
    __shared__ float s_sbn;
    if (t == 0) s_sbn = bm / 127.0f + 1e-8f;
    __syncthreads();
    float sbn = s_sbn, sa1 = s_sa1;
    float inv = 1.0f / sa1;
    sw1s[t] = qclipf(rintf(w1t / sbn), -128.0f, 127.0f) * sbn;
    float scb = s_in_p[0] * sbn;
    sb1s[t] = rintf(b1t / scb) * scb;
    if (t < 128) {
        float sc = sa1 * g_sw1[t];
        sc1[t] = sc;
        sb1[t] = rintf(g_bf[t] / sc) * sc;
    }

    // W chunk 0 via cp.async
    #pragma unroll
    for (int i = 0; i < 4; i++) {
        int lin = t + 256 * i;
        int oc = lin >> 3, j = lin & 7;
        cp16(smem_u32(Wb + oc * 72 + j * 8),
             (const void*)(((const uint4*)(g_w1cb + oc * 256)) + j));
    }
    cp_commit();
    __syncthreads();   // scales + sw1s visible

    // X staging: 8192 = 64 kwords x 128 px
    #pragma unroll
    for (int i = 0; i < 32; i++) {
        int lin = t + 256 * i;
        int k = lin >> 7, px = lin & 127;
        int pglob = p0 + px;
        int b = pglob / HW;
        int s = pglob - b * HW;
        const float* bp = batch + ((size_t)(b * CIN + 4 * k)) * HW + s;
        float f0 = bp[0], f1 = bp[HW], f2 = bp[2 * HW], f3 = bp[3 * HW];
        float4 wv = *(const float4*)&sw1s[4 * k];
        float4 bv = *(const float4*)&sb1s[4 * k];
        float q0 = qclipf(rintf(fmaxf(fmaf(f0, wv.x, bv.x), 0.0f) * inv), 0.0f, 127.0f);
        float q1 = qclipf(rintf(fmaxf(fmaf(f1, wv.y, bv.y), 0.0f) * inv), 0.0f, 127.0f);
        float q2 = qclipf(rintf(fmaxf(fmaf(f2, wv.z, bv.z), 0.0f) * inv), 0.0f, 127.0f);
        float q3 = qclipf(rintf(fmaxf(fmaf(f3, wv.w, bv.w), 0.0f) * inv), 0.0f, 127.0f);
        __nv_bfloat162 h01 = __floats2bfloat162_rn(q0, q1);
        __nv_bfloat162 h23 = __floats2bfloat162_rn(q2, q3);
        uint2 pk;
        pk.x = *(uint32_t*)&h01;
        pk.y = *(uint32_t*)&h23;
        *(uint2*)(Xs + px * 264 + 4 * k) = pk;
    }
    cp_wait0();
    __syncthreads();

    // 8 warps = 2 px-groups(64) x 4 oc-groups(32)
    int wid = t >> 5, l = t & 31;
    int pxg = wid & 1, ocg = wid >> 1;
    uint32_t xs0 = smem_u32(Xs), wb0 = smem_u32(Wb);

    uint32_t aaddr[4], boff4[2];
    #pragma unroll
    for (int mf = 0; mf < 4; mf++)
        aaddr[mf] = xs0 + ((pxg * 64 + mf * 16 + (l & 15)) * 264 + (l >> 4) * 8) * 2;
    #pragma unroll
    for (int np = 0; np < 2; np++)
        boff4[np] = ((ocg * 32 + np * 16 + ((l >> 4) & 1) * 8 + (l & 7)) * 72
                     + ((l >> 3) & 1) * 8) * 2;

    float acc[4][4][4];
    #pragma unroll
    for (int mf = 0; mf < 4; mf++)
        #pragma unroll
        for (int nf = 0; nf < 4; nf++)
            #pragma unroll
            for (int r = 0; r < 4; r++) acc[mf][nf][r] = 0.0f;

    #pragma unroll 1
    for (int c = 0; c < 4; c++) {
        if (c < 3) {
            int p1 = (c + 1) & 1;
            #pragma unroll
            for (int i = 0; i < 4; i++) {
                int lin = t + 256 * i;
                int oc = lin >> 3, j = lin & 7;
                cp16(smem_u32(Wb + p1 * 128 * 72 + oc * 72 + j * 8),
                     (const void*)(((const uint4*)(g_w1cb + oc * 256 + (c + 1) * 64)) + j));
            }
            cp_commit();
        }
        uint32_t wbp = wb0 + (uint32_t)((c & 1) * 128 * 72 * 2);
        #pragma unroll
        for (int ksl = 0; ksl < 4; ksl++) {
            int ks = c * 4 + ksl;
            uint32_t a[4][4], bfr[4][2];
            #pragma unroll
            for (int mf = 0; mf < 4; mf++)
                ldsm_x4(a[mf][0], a[mf][1], a[mf][2], a[mf][3], aaddr[mf] + ks * 32);
            #pragma unroll
            for (int np = 0; np < 2; np++)
                ldsm_x4(bfr[2*np][0], bfr[2*np][1], bfr[2*np+1][0], bfr[2*np+1][1],
                        wbp + boff4[np] + ksl * 32);
            #pragma unroll
            for (int mf = 0; mf < 4; mf++)
                #pragma unroll
                for (int nf = 0; nf < 4; nf++)
                    mma_bf16(acc[mf][nf], a[mf], bfr[nf]);
        }
        cp_wait0();
        __syncthreads();
    }

    // epilogue: scale+bias+relu into smem [128 px][132], then coalesced write
    float* outs = (float*)Xs;
    float m = 0.0f;
    #pragma unroll
    for (int mf = 0; mf < 4; mf++) {
        int pxl = pxg * 64 + mf * 16 + (l >> 2);
        #pragma unroll
        for (int nf = 0; nf < 4; nf++) {
            int oc = ocg * 32 + nf * 8 + (l & 3) * 2;
            float s0 = sc1[oc], s1 = sc1[oc + 1];
            float bb0 = sb1[oc], bb1 = sb1[oc + 1];
            float v0 = fmaxf(fmaf(acc[mf][nf][0], s0, bb0), 0.0f);
            float v1 = fmaxf(fmaf(acc[mf][nf][1], s1, bb1), 0.0f);
            float v2 = fmaxf(fmaf(acc[mf][nf][2], s0, bb0), 0.0f);
            float v3 = fmaxf(fmaf(acc[mf][nf][3], s1, bb1), 0.0f);
            m = fmaxf(m, fmaxf(fmaxf(v0, v1), fmaxf(v2, v3)));
            *(float2*)&outs[pxl * 132 + oc]       = make_float2(v0, v1);
            *(float2*)&outs[(pxl + 8) * 132 + oc] = make_float2(v2, v3);
        }
    }
    __syncthreads();
    #pragma unroll
    for (int i = 0; i < 16; i++) {
        int lin = t + 256 * i;
        int pxl = lin >> 5, j = lin & 31;
        float4 v = *(float4*)&outs[pxl * 132 + j * 4];
        *(float4*)&g_x2[(size_t)(p0 + pxl) * 128 + j * 4] = v;
    }
    float bm2 = blockReduceMax(m);
    if (t == 0) g_pmax2[blockIdx.x] = bm2;
}

// ---- K3: conv2 3x3 via bf16 mma, 2-row tiles (grid 28x32), fused quant ----
// 256 threads: warps 0-6 mma (16 px each, 112 px), warp 7 = W producer.
__global__ __launch_bounds__(256, 2) void k_conv2(float* __restrict__ out)
{
    extern __shared__ __nv_bfloat16 smem2[];
    __nv_bfloat16* Xs = smem2;                          // [4 rows][58][136] = 31552 el
    __nv_bfloat16* Wb = smem2 + 4 * 58 * 136;           // [2][32 oc][136]
    float* scmb = (float*)(Wb + 2 * 32 * 136);          // 32
    int t = threadIdx.x;
    int h0 = blockIdx.x * 2, b = blockIdx.y;

    // sa2 from conv1 partials
    float a2 = 0.0f;
    for (int i = t; i < 784; i += 256) a2 = fmaxf(a2, g_pmax2[i]);
    float r2 = blockReduceMax(a2);
    __shared__ float s_sa2;
    if (t == 0) s_sa2 = r2 / 127.0f + 1e-8f;
    __syncthreads();
    float sa2 = s_sa2;
    float inv2 = 1.0f / sa2;
    if (t < 32) scmb[t] = sa2 * g_sw2[t];

    // W tap 0 via cp.async (overlaps X staging): 512 chunks over 256 thr
    #pragma unroll
    for (int i = 0; i < 2; i++) {
        int idx = t + 256 * i;
        int oc = idx >> 4, j = idx & 15;
        cp16(smem_u32(Wb + oc * 136 + j * 8),
             (const void*)(((const uint4*)(g_w2cb + oc * 1160)) + j));
    }
    cp_commit();
    // X staging with fused quantization: 4*58*32 = 7424 words
    for (int lin = t; lin < 4 * 58 * 32; lin += 256) {
        int cell = lin >> 5, j = lin & 31;
        int row = cell / 58, col = cell - row * 58;
        int hh = h0 + row - 1;
        float4 v = make_float4(0.0f, 0.0f, 0.0f, 0.0f);
        if (col >= 1 && col <= 56 && hh >= 0 && hh < 56)
            v = ((const float4*)(g_x2 + (size_t)(b * HW + hh * 56 + col - 1) * 128))[j];
        float q0 = qclipf(rintf(v.x * inv2), 0.0f, 127.0f);
        float q1 = qclipf(rintf(v.y * inv2), 0.0f, 127.0f);
        float q2 = qclipf(rintf(v.z * inv2), 0.0f, 127.0f);
        float q3 = qclipf(rintf(v.w * inv2), 0.0f, 127.0f);
        __nv_bfloat162 h01 = __floats2bfloat162_rn(q0, q1);
        __nv_bfloat162 h23 = __floats2bfloat162_rn(q2, q3);
        uint2 pk;
        pk.x = *(uint32_t*)&h01;
        pk.y = *(uint32_t*)&h23;
        *(uint2*)(Xs + cell * 136 + j * 4) = pk;
    }
    cp_wait0();
    __syncthreads();

    int wid = t >> 5, l = t & 31;
    float m = 0.0f;
    float vv[4][4];

    if (wid == 7) {
        // producer: stage W taps 1..8, double buffered (one warp, 512 chunks)
        #pragma unroll 1
        for (int tap = 1; tap <= 8; tap++) {
            int bsel = tap & 1;
            if (tap >= 2) bar_sync256(3 + bsel);
            #pragma unroll
            for (int i = 0; i < 16; i++) {
                int idx = l + 32 * i;                  // 512 chunks
                int oc = idx >> 4, j = idx & 15;
                cp16(smem_u32(Wb + bsel * 32 * 136 + oc * 136 + j * 8),
                     (const void*)(((const uint4*)(g_w2cb + oc * 1160 + tap * 128)) + j));
            }
            cp_commit();
            cp_wait0();
            bar_arrive256(1 + bsel);
        }
    } else {
        // consumers: 7 mma warps, A-fragment prefetch inside tap
        uint32_t xs0 = smem_u32(Xs), wb0 = smem_u32(Wb);
        int px = wid * 16 + (l & 15);
        int hl = px / 56, ww = px - hl * 56;
        uint32_t abase = xs0 + ((hl * 58 + ww) * 136 + (l >> 4) * 8) * 2;
        uint32_t boff4[2];
        #pragma unroll
        for (int np = 0; np < 2; np++)
            boff4[np] = ((np * 16 + ((l >> 4) & 1) * 8 + (l & 7)) * 136
                         + ((l >> 3) & 1) * 8) * 2;

        float acc[4][4];
        #pragma unroll
        for (int nf = 0; nf < 4; nf++)
            #pragma unroll
            for (int r = 0; r < 4; r++) acc[nf][r] = 0.0f;

        #pragma unroll 1
        for (int tap = 0; tap <= 8; tap++) {
            int bsel = tap & 1;
            if (tap >= 1) bar_sync256(1 + bsel);
            uint32_t toff = (uint32_t)(((tap / 3) * 58 + (tap % 3)) * 136 * 2);
            uint32_t wbp = wb0 + (uint32_t)(bsel * 32 * 136 * 2);
            uint32_t acur[4];
            ldsm_x4(acur[0], acur[1], acur[2], acur[3], abase + toff);
            #pragma unroll
            for (int ks = 0; ks < 8; ks++) {
                uint32_t bfr[4][2], anx[4];
                #pragma unroll
                for (int np = 0; np < 2; np++)
                    ldsm_x4(bfr[2*np][0], bfr[2*np][1], bfr[2*np+1][0], bfr[2*np+1][1],
                            wbp + boff4[np] + ks * 32);
                if (ks < 7)
                    ldsm_x4(anx[0], anx[1], anx[2], anx[3], abase + toff + (ks + 1) * 32);
                #pragma unroll
                for (int nf = 0; nf < 4; nf++)
                    mma_bf16(acc[nf], acur, bfr[nf]);
                if (ks < 7) {
                    acur[0] = anx[0]; acur[1] = anx[1];
                    acur[2] = anx[2]; acur[3] = anx[3];
                }
            }
            bar_arrive256(3 + bsel);
        }
        #pragma unroll
        for (int nf = 0; nf < 4; nf++) {
            int oc = nf * 8 + (l & 3) * 2;
            float s0 = scmb[oc], s1 = scmb[oc + 1];
            vv[nf][0] = acc[nf][0] * s0;
            vv[nf][1] = acc[nf][1] * s1;
            vv[nf][2] = acc[nf][2] * s0;
            vv[nf][3] = acc[nf][3] * s1;
            m = fmaxf(m, fmaxf(fmaxf(fabsf(vv[nf][0]), fabsf(vv[nf][1])),
                               fmaxf(fabsf(vv[nf][2]), fabsf(vv[nf][3]))));
        }
    }
    __syncthreads();
    float* outs = (float*)Xs;         // [32 oc][116] floats = 14848B
    if (wid < 7) {
        int pxo = wid * 16 + (l >> 2);
        #pragma unroll
        for (int nf = 0; nf < 4; nf++) {
            int oc = nf * 8 + (l & 3) * 2;
            outs[oc * 116 + pxo]           = vv[nf][0];
            outs[(oc + 1) * 116 + pxo]     = vv[nf][1];
            outs[oc * 116 + pxo + 8]       = vv[nf][2];
            outs[(oc + 1) * 116 + pxo + 8] = vv[nf][3];
        }
    }
    __syncthreads();
    size_t obase = ((size_t)b * 288 + 256) * HW + h0 * 56;
    for (int lin = t; lin < 32 * 28; lin += 256) {     // 896 float4 (112 fl/oc)
        int oc = lin / 28, j = lin - oc * 28;
        float4 v = *(float4*)(outs + oc * 116 + j * 4);
        *(float4*)(out + obase + (size_t)oc * HW + j * 4) = v;
    }
    float bm = blockReduceMax(m);
    if (t == 0) g_pmaxy[blockIdx.y * 28 + blockIdx.x] = bm;
}

// ------ K4: output requant, plane-per-block, MLP=4, streaming hints --------
__global__ __launch_bounds__(256) void k_out(const float4* __restrict__ batch4,
                                             float4* __restrict__ out4,
                                             float* __restrict__ out, int out_size)
{
    int c = blockIdx.x, b = blockIdx.y;
    int t = threadIdx.x;
    float ay = 0.0f;
    for (int i = t; i < 896; i += 256) ay = fmaxf(ay, g_pmaxy[i]);
    float ry = blockReduceMax(ay);
    __shared__ float s_s;
    if (t == 0) s_s = fmaxf(g_maxb_f, ry) / 127.0f + 1e-8f;
    __syncthreads();
    float s = s_s;
    float inv = 1.0f / s;
    float4* dst = out4 + (b * 288 + c) * HW4;
    const float4* src = (c < CIN) ? (batch4 + (b * CIN + c) * HW4) : dst;
    float4 v0 = __ldcs(&src[t]), v1 = __ldcs(&src[t + 256]), v2 = __ldcs(&src[t + 512]);
    bool has3 = t < (HW4 - 768);
    float4 v3 = has3 ? __ldcs(&src[t + 768]) : make_float4(0.0f, 0.0f, 0.0f, 0.0f);
    #define RQ(v) do { \
        v.x = qclipf(rintf(v.x * inv), -128.0f, 127.0f) * s; \
        v.y = qclipf(rintf(v.y * inv), -128.0f, 127.0f) * s; \
        v.z = qclipf(rintf(v.z * inv), -128.0f, 127.0f) * s; \
        v.w = qclipf(rintf(v.w * inv), -128.0f, 127.0f) * s; } while (0)
    RQ(v0); RQ(v1); RQ(v2);
    __stcs(&dst[t], v0); __stcs(&dst[t + 256], v1); __stcs(&dst[t + 512], v2);
    if (has3) { RQ(v3); __stcs(&dst[t + 768], v3); }
    #undef RQ
    if (c == 0 && b == 0 && t == 0)
        for (int k = N_OUT; k < out_size; k++) out[k] = s;
}

extern "C" void kernel_launch(void* const* d_in, const int* in_sizes, int n_in,
                              void* d_out, int out_size)
{
    const float* batch = (const float*)d_in[0];
    const float* s_in  = (const float*)d_in[1];
    const float* g1    = (const float*)d_in[2];
    const float* be1   = (const float*)d_in[3];
    const float* m1    = (const float*)d_in[4];
    const float* v1    = (const float*)d_in[5];
    const float* w1c   = (const float*)d_in[6];
    const float* g2    = (const float*)d_in[7];
    const float* be2   = (const float*)d_in[8];
    const float* m2    = (const float*)d_in[9];
    const float* v2    = (const float*)d_in[10];
    const float* w2c   = (const float*)d_in[11];
    float* out = (float*)d_out;

    const int CONV1_SMEM = 128 * 264 * 2 + 2 * 128 * 72 * 2
                         + (128 + 128 + 256 + 256) * 4;                 // 107520
    const int CONV2_SMEM = (4 * 58 * 136 + 2 * 32 * 136) * 2 + 32 * 4;  // 80640
    static bool attr_done = false;
    if (!attr_done) {
        cudaFuncSetAttribute(k_conv1, cudaFuncAttributeMaxDynamicSharedMemorySize, CONV1_SMEM);
        cudaFuncSetAttribute(k_conv2, cudaFuncAttributeMaxDynamicSharedMemorySize, CONV2_SMEM);
        attr_done = true;
    }

    k_max1<<<dim3(CIN + 2, B_N), 256>>>((const float4*)batch, g1, be1, m1, v1,
                                        s_in, w1c, g2, be2, m2, v2, w2c);  // 0
    k_conv1<<<PX / 128, 256, CONV1_SMEM>>>(batch, g1, be1, m1, v1, s_in);  // 1
    k_conv2<<<dim3(28, 32), 256, CONV2_SMEM>>>(out);                       // 2
    k_out<<<dim3(288, B_N), 256>>>((const float4*)batch, (float4*)out, out, out_size);
}

// round 17
// speedup vs baseline: 1.0520x; 1.0520x over previous
#include <cuda_runtime.h>
#include <cuda_bf16.h>
#include <cstdint>

#define B_N   32
#define CIN   256
#define HW    3136
#define HW4   784
#define PX    100352          // B_N*HW
#define CO1   128
#define CO2   32
#define N_OUT (32*288*3136)

// ---------------- scratch (device globals; no allocations) ----------------
__device__ float    g_bf[CO1], g_sw1[CO1];
__device__ __nv_bfloat16 g_w1cb[CO1*256];   // conv1 weight codes bf16 [oc][k]
__device__ float    g_sw2[CO2];
__device__ __nv_bfloat16 g_w2cb[CO2*1160];  // conv2 weight codes bf16 [oc][tap*128+ci]
__device__ float    g_pmax1[8192], g_pmaxb[8192];   // per-block partials (no init needed)
__device__ float    g_pmax2[784];
__device__ float    g_pmaxy[448];
__device__ float    g_maxb_f;                        // same-value multi-writer
__device__ float    g_x2[PX*CO1];           // conv1 out fp32 NHWC (51.4MB)

// ---------------- helpers ----------------
__device__ __forceinline__ float warpMax(float v) {
    #pragma unroll
    for (int o = 16; o; o >>= 1) v = fmaxf(v, __shfl_xor_sync(0xffffffffu, v, o));
    return v;
}
__device__ __forceinline__ float blockReduceMax(float v) {
    __shared__ float sm[16];
    float w = warpMax(v);
    if ((threadIdx.x & 31) == 0) sm[threadIdx.x >> 5] = w;
    __syncthreads();
    float r = (threadIdx.x < (blockDim.x >> 5)) ? sm[threadIdx.x] : 0.0f;
    r = warpMax(r);
    __syncthreads();
    return r;  // valid in warp 0
}
__device__ __forceinline__ float qclipf(float q, float lo, float hi) {
    return fminf(fmaxf(q, lo), hi);
}
__device__ __forceinline__ uint32_t smem_u32(const void* p) {
    return (uint32_t)__cvta_generic_to_shared(p);
}
__device__ __forceinline__ void ldsm_x4(uint32_t& r0, uint32_t& r1,
                                        uint32_t& r2, uint32_t& r3, uint32_t a) {
    asm volatile("ldmatrix.sync.aligned.m8n8.x4.shared.b16 {%0,%1,%2,%3}, [%4];"
                 : "=r"(r0), "=r"(r1), "=r"(r2), "=r"(r3) : "r"(a));
}
__device__ __forceinline__ void mma_bf16(float* d, const uint32_t* a, const uint32_t* b) {
    asm volatile(
        "mma.sync.aligned.m16n8k16.row.col.f32.bf16.bf16.f32 "
        "{%0,%1,%2,%3},{%4,%5,%6,%7},{%8,%9},{%0,%1,%2,%3};"
        : "+f"(d[0]), "+f"(d[1]), "+f"(d[2]), "+f"(d[3])
        : "r"(a[0]), "r"(a[1]), "r"(a[2]), "r"(a[3]), "r"(b[0]), "r"(b[1]));
}
__device__ __forceinline__ void cp16(uint32_t dst, const void* src) {
    asm volatile("cp.async.cg.shared.global [%0], [%1], 16;" :: "r"(dst), "l"(src));
}
__device__ __forceinline__ void cp_commit() {
    asm volatile("cp.async.commit_group;");
}
__device__ __forceinline__ void cp_wait0() {
    asm volatile("cp.async.wait_group 0;" ::: "memory");
}
__device__ __forceinline__ void bar_sync(int id) {
    asm volatile("bar.sync %0, 512;" :: "r"(id) : "memory");
}
__device__ __forceinline__ void bar_arrive(int id) {
    asm volatile("bar.arrive %0, 512;" :: "r"(id) : "memory");
}

// ---- K1: max relu(bn1(batch)) + max|batch| per plane, plus weight-prep blocks ----
__global__ __launch_bounds__(256) void k_max1(
    const float4* __restrict__ batch4,
    const float* __restrict__ g1, const float* __restrict__ be1,
    const float* __restrict__ m1, const float* __restrict__ v1,
    const float* __restrict__ s_in_p,
    const float* __restrict__ w1c, const float* __restrict__ g2,
    const float* __restrict__ be2, const float* __restrict__ m2,
    const float* __restrict__ v2, const float* __restrict__ w2c)
{
    int ci = blockIdx.x, b = blockIdx.y;
    int t = threadIdx.x;
    int w = t >> 5, l = t & 31;

    if (ci >= CIN) {
        if (b) return;
        if (ci == CIN) {
            // conv1 weight quantization (warp per oc group)
            for (int o = w; o < CO1; o += 8) {
                float tt = g2[o] / sqrtf(v2[o] + 1e-5f);
                const float* wr = w1c + o * CIN;
                float mx = 0.0f;
                #pragma unroll
                for (int i = 0; i < 8; i++) mx = fmaxf(mx, fabsf(wr[l + 32 * i] * tt));
                mx = warpMax(mx);
                float s = mx / 127.0f + 1e-8f;
                if (l == 0) { g_sw1[o] = s; g_bf[o] = be2[o] - m2[o] * tt; }
                #pragma unroll
                for (int i = 0; i < 8; i++) {
                    int c = l + 32 * i;
                    float code = qclipf(rintf(wr[c] * tt / s), -128.0f, 127.0f);
                    g_w1cb[o * 256 + c] = __float2bfloat16(code);
                }
            }
        } else {
            // conv2 weight quantization
            for (int o = w; o < CO2; o += 8) {
                const float* wr = w2c + o * 1152;
                float mx = 0.0f;
                #pragma unroll
                for (int i = 0; i < 36; i++) mx = fmaxf(mx, fabsf(wr[l + 32 * i]));
                mx = warpMax(mx);
                float s = mx / 127.0f + 1e-8f;
                if (l == 0) g_sw2[o] = s;
                #pragma unroll
                for (int i = 0; i < 36; i++) {
                    int j = l + 32 * i;
                    int tap = j >> 7, cc = j & 127;
                    float code = qclipf(rintf(wr[cc * 9 + tap] / s), -128.0f, 127.0f);
                    g_w2cb[o * 1160 + j] = __float2bfloat16(code);
                }
            }
        }
        return;
    }

    // bn1 fold (in-block, bit-identical to old prep)
    float w1t = g1[t] / sqrtf(v1[t] + 1e-5f);
    float bm = blockReduceMax(fabsf(w1t));
    __shared__ float s_sbn;
    if (t == 0) s_sbn = bm / 127.0f + 1e-8f;
    __syncthreads();
    float sbn = s_sbn;
    float w1i = g1[ci] / sqrtf(v1[ci] + 1e-5f);
    float b1i = be1[ci] - m1[ci] * w1i;
    float wq = qclipf(rintf(w1i / sbn), -128.0f, 127.0f) * sbn;
    float scb = s_in_p[0] * sbn;
    float bq = rintf(b1i / scb) * scb;

    const float4* p = batch4 + (b * CIN + ci) * HW4;
    float4 v0 = p[t], vA = p[t + 256], vB = p[t + 512];
    bool has3 = t < (HW4 - 768);
    float4 vC = has3 ? p[t + 768] : make_float4(0.0f, 0.0f, 0.0f, 0.0f);
    float m1v = 0.0f, mb = 0.0f;
    #define M1(v) do { \
        m1v = fmaxf(m1v, fmaxf(fmaf(v.x, wq, bq), 0.0f)); \
        m1v = fmaxf(m1v, fmaxf(fmaf(v.y, wq, bq), 0.0f)); \
        m1v = fmaxf(m1v, fmaxf(fmaf(v.z, wq, bq), 0.0f)); \
        m1v = fmaxf(m1v, fmaxf(fmaf(v.w, wq, bq), 0.0f)); \
        mb = fmaxf(mb, fmaxf(fmaxf(fabsf(v.x), fabsf(v.y)), \
                             fmaxf(fabsf(v.z), fabsf(v.w)))); } while (0)
    M1(v0); M1(vA); M1(vB);
    if (has3) M1(vC);
    #undef M1
    float r1 = blockReduceMax(m1v);
    if (t == 0) g_pmax1[b * CIN + ci] = r1;
    float rb = blockReduceMax(mb);
    if (t == 0) g_pmaxb[b * CIN + ci] = rb;
}

// ---- K2: fused bn1+quant + 1x1 conv via bf16 mma (128px x 128oc, K=256) ----
__global__ __launch_bounds__(256, 2) void k_conv1(
    const float* __restrict__ batch,
    const float* __restrict__ g1, const float* __restrict__ be1,
    const float* __restrict__ m1, const float* __restrict__ v1,
    const float* __restrict__ s_in_p)
{
    extern __shared__ __nv_bfloat16 smemb[];
    __nv_bfloat16* Xs = smemb;                          // [128 px][264]
    __nv_bfloat16* Wb = smemb + 128 * 264;              // [2][128 oc][72]
    float* sc1  = (float*)(smemb + 128 * 264 + 2 * 128 * 72);
    float* sb1  = sc1 + 128;
    float* sw1s = sb1 + 128;                            // 256
    float* sb1s = sw1s + 256;                           // 256
    int t = threadIdx.x;
    int p0 = blockIdx.x * 128;

    // reduce partials: sa1 (needed) + maxb (service for k_out)
    float a1 = 0.0f, ab = 0.0f;
    #pragma unroll 4
    for (int i = t; i < 8192; i += 256) {
        a1 = fmaxf(a1, g_pmax1[i]);
        ab = fmaxf(ab, g_pmaxb[i]);
    }
    float r1 = blockReduceMax(a1);
    __shared__ float s_sa1;
    if (t == 0) s_sa1 = r1 / 127.0f + 1e-8f;
    float rb = blockReduceMax(ab);
    if (t == 0) g_maxb_f = rb;          // identical value from every block

    // bn1 fold into smem (bit-identical math)
    float w1t = g1[t] / sqrtf(v1[t] + 1e-5f);
    float b1t = be1[t] - m1[t] * w1t;
    float bm = blockReduceMax(fabsf(w1t));
    __shared__ float s_sbn;
    if (t == 0) s_sbn = bm / 127.0f + 1e-8f;
    __syncthreads();
    float sbn = s_sbn, sa1 = s_sa1;
    float inv = 1.0f / sa1;
    sw1s[t] = qclipf(rintf(w1t / sbn), -128.0f, 127.0f) * sbn;
    float scb = s_in_p[0] * sbn;
    sb1s[t] = rintf(b1t / scb) * scb;
    if (t < 128) {
        float sc = sa1 * g_sw1[t];
        sc1[t] = sc;
        sb1[t] = rintf(g_bf[t] / sc) * sc;
    }

    // W chunk 0 via cp.async
    #pragma unroll
    for (int i = 0; i < 4; i++) {
        int lin = t + 256 * i;
        int oc = lin >> 3, j = lin & 7;
        cp16(smem_u32(Wb + oc * 72 + j * 8),
             (const void*)(((const uint4*)(g_w1cb + oc * 256)) + j));
    }
    cp_commit();
    __syncthreads();   // scales + sw1s visible

    // X staging: 8192 = 64 kwords x 128 px
    #pragma unroll
    for (int i = 0; i < 32; i++) {
        int lin = t + 256 * i;
        int k = lin >> 7, px = lin & 127;
        int pglob = p0 + px;
        int b = pglob / HW;
        int s = pglob - b * HW;
        const float* bp = batch + ((size_t)(b * CIN + 4 * k)) * HW + s;
        float f0 = bp[0], f1 = bp[HW], f2 = bp[2 * HW], f3 = bp[3 * HW];
        float4 wv = *(const float4*)&sw1s[4 * k];
        float4 bv = *(const float4*)&sb1s[4 * k];
        float q0 = qclipf(rintf(fmaxf(fmaf(f0, wv.x, bv.x), 0.0f) * inv), 0.0f, 127.0f);
        float q1 = qclipf(rintf(fmaxf(fmaf(f1, wv.y, bv.y), 0.0f) * inv), 0.0f, 127.0f);
        float q2 = qclipf(rintf(fmaxf(fmaf(f2, wv.z, bv.z), 0.0f) * inv), 0.0f, 127.0f);
        float q3 = qclipf(rintf(fmaxf(fmaf(f3, wv.w, bv.w), 0.0f) * inv), 0.0f, 127.0f);
        __nv_bfloat162 h01 = __floats2bfloat162_rn(q0, q1);
        __nv_bfloat162 h23 = __floats2bfloat162_rn(q2, q3);
        uint2 pk;
        pk.x = *(uint32_t*)&h01;
        pk.y = *(uint32_t*)&h23;
        *(uint2*)(Xs + px * 264 + 4 * k) = pk;
    }
    cp_wait0();
    __syncthreads();

    int wid = t >> 5, l = t & 31;
    int pxg = wid & 1, ocg = wid >> 1;
    uint32_t xs0 = smem_u32(Xs), wb0 = smem_u32(Wb);

    uint32_t aaddr[4], boff4[2];
    #pragma unroll
    for (int mf = 0; mf < 4; mf++)
        aaddr[mf] = xs0 + ((pxg * 64 + mf * 16 + (l & 15)) * 264 + (l >> 4) * 8) * 2;
    #pragma unroll
    for (int np = 0; np < 2; np++)
        boff4[np] = ((ocg * 32 + np * 16 + ((l >> 4) & 1) * 8 + (l & 7)) * 72
                     + ((l >> 3) & 1) * 8) * 2;

    float acc[4][4][4];
    #pragma unroll
    for (int mf = 0; mf < 4; mf++)
        #pragma unroll
        for (int nf = 0; nf < 4; nf++)
            #pragma unroll
            for (int r = 0; r < 4; r++) acc[mf][nf][r] = 0.0f;

    #pragma unroll 1
    for (int c = 0; c < 4; c++) {
        if (c < 3) {
            int p1 = (c + 1) & 1;
            #pragma unroll
            for (int i = 0; i < 4; i++) {
                int lin = t + 256 * i;
                int oc = lin >> 3, j = lin & 7;
                cp16(smem_u32(Wb + p1 * 128 * 72 + oc * 72 + j * 8),
                     (const void*)(((const uint4*)(g_w1cb + oc * 256 + (c + 1) * 64)) + j));
            }
            cp_commit();
        }
        uint32_t wbp = wb0 + (uint32_t)((c & 1) * 128 * 72 * 2);
        #pragma unroll
        for (int ksl = 0; ksl < 4; ksl++) {
            int ks = c * 4 + ksl;
            uint32_t a[4][4], bfr[4][2];
            #pragma unroll
            for (int mf = 0; mf < 4; mf++)
                ldsm_x4(a[mf][0], a[mf][1], a[mf][2], a[mf][3], aaddr[mf] + ks * 32);
            #pragma unroll
            for (int np = 0; np < 2; np++)
                ldsm_x4(bfr[2*np][0], bfr[2*np][1], bfr[2*np+1][0], bfr[2*np+1][1],
                        wbp + boff4[np] + ksl * 32);
            #pragma unroll
            for (int mf = 0; mf < 4; mf++)
                #pragma unroll
                for (int nf = 0; nf < 4; nf++)
                    mma_bf16(acc[mf][nf], a[mf], bfr[nf]);
        }
        cp_wait0();
        __syncthreads();
    }

    // epilogue: scale+bias+relu into smem [128 px][132], then coalesced write
    float* outs = (float*)Xs;
    float m = 0.0f;
    #pragma unroll
    for (int mf = 0; mf < 4; mf++) {
        int pxl = pxg * 64 + mf * 16 + (l >> 2);
        #pragma unroll
        for (int nf = 0; nf < 4; nf++) {
            int oc = ocg * 32 + nf * 8 + (l & 3) * 2;
            float s0 = sc1[oc], s1 = sc1[oc + 1];
            float bb0 = sb1[oc], bb1 = sb1[oc + 1];
            float v0 = fmaxf(fmaf(acc[mf][nf][0], s0, bb0), 0.0f);
            float v1 = fmaxf(fmaf(acc[mf][nf][1], s1, bb1), 0.0f);
            float v2 = fmaxf(fmaf(acc[mf][nf][2], s0, bb0), 0.0f);
            float v3 = fmaxf(fmaf(acc[mf][nf][3], s1, bb1), 0.0f);
            m = fmaxf(m, fmaxf(fmaxf(v0, v1), fmaxf(v2, v3)));
            *(float2*)&outs[pxl * 132 + oc]       = make_float2(v0, v1);
            *(float2*)&outs[(pxl + 8) * 132 + oc] = make_float2(v2, v3);
        }
    }
    __syncthreads();
    #pragma unroll
    for (int i = 0; i < 16; i++) {
        int lin = t + 256 * i;
        int pxl = lin >> 5, j = lin & 31;
        float4 v = *(float4*)&outs[pxl * 132 + j * 4];
        *(float4*)&g_x2[(size_t)(p0 + pxl) * 128 + j * 4] = v;
    }
    float bm2 = blockReduceMax(m);
    if (t == 0) g_pmax2[blockIdx.x] = bm2;
}

// ---- K3: conv2 3x3 via bf16 mma, fused quant, producer/consumer W pipeline ----
__global__ __launch_bounds__(512, 2) void k_conv2(float* __restrict__ out)
{
    extern __shared__ __nv_bfloat16 smem2[];
    __nv_bfloat16* Xs = smem2;                          // [6][58][136]
    __nv_bfloat16* Wb = smem2 + 6 * 58 * 136;           // [2][32 oc][136]
    float* scmb = (float*)(Wb + 2 * 32 * 136);          // 32
    int t = threadIdx.x;
    int h0 = blockIdx.x * 4, b = blockIdx.y;

    // sa2 from conv1 partials
    float a2 = 0.0f;
    for (int i = t; i < 784; i += 512) a2 = fmaxf(a2, g_pmax2[i]);
    float r2 = blockReduceMax(a2);
    __shared__ float s_sa2;
    if (t == 0) s_sa2 = r2 / 127.0f + 1e-8f;
    __syncthreads();
    float sa2 = s_sa2;
    float inv2 = 1.0f / sa2;
    if (t < 32) scmb[t] = sa2 * g_sw2[t];

    // W tap 0 via cp.async (overlaps X staging)
    {
        int oc = t >> 4, j = t & 15;
        cp16(smem_u32(Wb + oc * 136 + j * 8),
             (const void*)(((const uint4*)(g_w2cb + oc * 1160)) + j));
        cp_commit();
    }
    // X staging with fused quantization
    for (int lin = t; lin < 6 * 58 * 32; lin += 512) {
        int cell = lin >> 5, j = lin & 31;
        int row = cell / 58, col = cell - row * 58;
        int hh = h0 + row - 1;
        float4 v = make_float4(0.0f, 0.0f, 0.0f, 0.0f);
        if (col >= 1 && col <= 56 && hh >= 0 && hh < 56)
            v = ((const float4*)(g_x2 + (size_t)(b * HW + hh * 56 + col - 1) * 128))[j];
        float q0 = qclipf(rintf(v.x * inv2), 0.0f, 127.0f);
        float q1 = qclipf(rintf(v.y * inv2), 0.0f, 127.0f);
        float q2 = qclipf(rintf(v.z * inv2), 0.0f, 127.0f);
        float q3 = qclipf(rintf(v.w * inv2), 0.0f, 127.0f);
        __nv_bfloat162 h01 = __floats2bfloat162_rn(q0, q1);
        __nv_bfloat162 h23 = __floats2bfloat162_rn(q2, q3);
        uint2 pk;
        pk.x = *(uint32_t*)&h01;
        pk.y = *(uint32_t*)&h23;
        *(uint2*)(Xs + cell * 136 + j * 4) = pk;
    }
    cp_wait0();
    __syncthreads();

    int wid = t >> 5, l = t & 31;
    float m = 0.0f;
    float vv[4][4];

    if (wid >= 14) {
        // producer: stage W taps 1..8, double buffered
        int pt = t - 448;
        #pragma unroll 1
        for (int tap = 1; tap <= 8; tap++) {
            int bsel = tap & 1;
            if (tap >= 2) bar_sync(3 + bsel);
            #pragma unroll
            for (int i = 0; i < 8; i++) {
                int idx = pt + 64 * i;
                int oc = idx >> 4, j = idx & 15;
                cp16(smem_u32(Wb + bsel * 32 * 136 + oc * 136 + j * 8),
                     (const void*)(((const uint4*)(g_w2cb + oc * 1160 + tap * 128)) + j));
            }
            cp_commit();
            cp_wait0();
            bar_arrive(1 + bsel);
        }
    } else {
        // consumers: 14 mma warps, A-fragment prefetch inside tap
        uint32_t xs0 = smem_u32(Xs), wb0 = smem_u32(Wb);
        int px = wid * 16 + (l & 15);
        int hl = px / 56, ww = px - hl * 56;
        uint32_t abase = xs0 + ((hl * 58 + ww) * 136 + (l >> 4) * 8) * 2;
        uint32_t boff4[2];
        #pragma unroll
        for (int np = 0; np < 2; np++)
            boff4[np] = ((np * 16 + ((l >> 4) & 1) * 8 + (l & 7)) * 136
                         + ((l >> 3) & 1) * 8) * 2;

        float acc[4][4];
        #pragma unroll
        for (int nf = 0; nf < 4; nf++)
            #pragma unroll
            for (int r = 0; r < 4; r++) acc[nf][r] = 0.0f;

        #pragma unroll 1
        for (int tap = 0; tap <= 8; tap++) {
            int bsel = tap & 1;
            if (tap >= 1) bar_sync(1 + bsel);
            uint32_t toff = (uint32_t)(((tap / 3) * 58 + (tap % 3)) * 136 * 2);
            uint32_t wbp = wb0 + (uint32_t)(bsel * 32 * 136 * 2);
            uint32_t acur[4];
            ldsm_x4(acur[0], acur[1], acur[2], acur[3], abase + toff);
            #pragma unroll
            for (int ks = 0; ks < 8; ks++) {
                uint32_t bfr[4][2], anx[4];
                #pragma unroll
                for (int np = 0; np < 2; np++)
                    ldsm_x4(bfr[2*np][0], bfr[2*np][1], bfr[2*np+1][0], bfr[2*np+1][1],
                            wbp + boff4[np] + ks * 32);
                if (ks < 7)
                    ldsm_x4(anx[0], anx[1], anx[2], anx[3], abase + toff + (ks + 1) * 32);
                #pragma unroll
                for (int nf = 0; nf < 4; nf++)
                    mma_bf16(acc[nf], acur, bfr[nf]);
                if (ks < 7) {
                    acur[0] = anx[0]; acur[1] = anx[1];
                    acur[2] = anx[2]; acur[3] = anx[3];
                }
            }
            bar_arrive(3 + bsel);
        }
        #pragma unroll
        for (int nf = 0; nf < 4; nf++) {
            int oc = nf * 8 + (l & 3) * 2;
            float s0 = scmb[oc], s1 = scmb[oc + 1];
            vv[nf][0] = acc[nf][0] * s0;
            vv[nf][1] = acc[nf][1] * s1;
            vv[nf][2] = acc[nf][2] * s0;
            vv[nf][3] = acc[nf][3] * s1;
            m = fmaxf(m, fmaxf(fmaxf(fabsf(vv[nf][0]), fabsf(vv[nf][1])),
                               fmaxf(fabsf(vv[nf][2]), fabsf(vv[nf][3]))));
        }
    }
    __syncthreads();
    float* outs = (float*)Xs;         // [32 oc][228] floats
    if (wid < 14) {
        int pxo = wid * 16 + (l >> 2);
        #pragma unroll
        for (int nf = 0; nf < 4; nf++) {
            int oc = nf * 8 + (l & 3) * 2;
            outs[oc * 228 + pxo]           = vv[nf][0];
            outs[(oc + 1) * 228 + pxo]     = vv[nf][1];
            outs[oc * 228 + pxo + 8]       = vv[nf][2];
            outs[(oc + 1) * 228 + pxo + 8] = vv[nf][3];
        }
    }
    __syncthreads();
    size_t obase = ((size_t)b * 288 + 256) * HW + h0 * 56;
    for (int lin = t; lin < 32 * 56; lin += 512) {
        int oc = lin / 56, j = lin - oc * 56;
        float4 v = *(float4*)(outs + oc * 228 + j * 4);
        *(float4*)(out + obase + (size_t)oc * HW + j * 4) = v;
    }
    float bm = blockReduceMax(m);
    if (t == 0) g_pmaxy[blockIdx.y * 14 + blockIdx.x] = bm;
}

// ------ K4: output requant, plane-per-block, MLP=4, streaming hints --------
__global__ __launch_bounds__(256) void k_out(const float4* __restrict__ batch4,
                                             float4* __restrict__ out4,
                                             float* __restrict__ out, int out_size)
{
    int c = blockIdx.x, b = blockIdx.y;
    int t = threadIdx.x;
    float ay = 0.0f;
    for (int i = t; i < 448; i += 256) ay = fmaxf(ay, g_pmaxy[i]);
    float ry = blockReduceMax(ay);
    __shared__ float s_s;
    if (t == 0) s_s = fmaxf(g_maxb_f, ry) / 127.0f + 1e-8f;
    __syncthreads();
    float s = s_s;
    float inv = 1.0f / s;
    float4* dst = out4 + (b * 288 + c) * HW4;
    const float4* src = (c < CIN) ? (batch4 + (b * CIN + c) * HW4) : dst;
    float4 v0 = __ldcs(&src[t]), v1 = __ldcs(&src[t + 256]), v2 = __ldcs(&src[t + 512]);
    bool has3 = t < (HW4 - 768);
    float4 v3 = has3 ? __ldcs(&src[t + 768]) : make_float4(0.0f, 0.0f, 0.0f, 0.0f);
    #define RQ(v) do { \
        v.x = qclipf(rintf(v.x * inv), -128.0f, 127.0f) * s; \
        v.y = qclipf(rintf(v.y * inv), -128.0f, 127.0f) * s; \
        v.z = qclipf(rintf(v.z * inv), -128.0f, 127.0f) * s; \
        v.w = qclipf(rintf(v.w * inv), -128.0f, 127.0f) * s; } while (0)
    RQ(v0); RQ(v1); RQ(v2);
    __stcs(&dst[t], v0); __stcs(&dst[t + 256], v1); __stcs(&dst[t + 512], v2);
    if (has3) { RQ(v3); __stcs(&dst[t + 768], v3); }
    #undef RQ
    if (c == 0 && b == 0 && t == 0)
        for (int k = N_OUT; k < out_size; k++) out[k] = s;
}

extern "C" void kernel_launch(void* const* d_in, const int* in_sizes, int n_in,
                              void* d_out, int out_size)
{
    const float* batch = (const float*)d_in[0];
    const float* s_in  = (const float*)d_in[1];
    const float* g1    = (const float*)d_in[2];
    const float* be1   = (const float*)d_in[3];
    const float* m1    = (const float*)d_in[4];
    const float* v1    = (const float*)d_in[5];
    const float* w1c   = (const float*)d_in[6];
    const float* g2    = (const float*)d_in[7];
    const float* be2   = (const float*)d_in[8];
    const float* m2    = (const float*)d_in[9];
    const float* v2    = (const float*)d_in[10];
    const float* w2c   = (const float*)d_in[11];
    float* out = (float*)d_out;

    const int CONV1_SMEM = 128 * 264 * 2 + 2 * 128 * 72 * 2
                         + (128 + 128 + 256 + 256) * 4;                 // 107520
    const int CONV2_SMEM = (6 * 58 * 136 + 2 * 32 * 136) * 2 + 32 * 4;  // 112192
    static bool attr_done = false;
    if (!attr_done) {
        cudaFuncSetAttribute(k_conv1, cudaFuncAttributeMaxDynamicSharedMemorySize, CONV1_SMEM);
        cudaFuncSetAttribute(k_conv2, cudaFuncAttributeMaxDynamicSharedMemorySize, CONV2_SMEM);
        attr_done = true;
    }

    k_max1<<<dim3(CIN + 2, B_N), 256>>>((const float4*)batch, g1, be1, m1, v1,
                                        s_in, w1c, g2, be2, m2, v2, w2c);  // 0
    k_conv1<<<PX / 128, 256, CONV1_SMEM>>>(batch, g1, be1, m1, v1, s_in);  // 1
    k_conv2<<<dim3(14, 32), 512, CONV2_SMEM>>>(out);                       // 2
    k_out<<<dim3(288, B_N), 256>>>((const float4*)batch, (float4*)out, out, out_size);
}